// round 6
// baseline (speedup 1.0000x reference)
#include <cuda_runtime.h>
#include <math.h>

#define TS 512
#define BN 128
#define IND 32
#define HN 512
#define ON 8
#define PN 64

// FX[t,b,h] = sum_i Win[h,i]*x[t,b,i]  (134 MB scratch)
__device__ float g_fx[(size_t)TS * BN * HN];
// Wr, j-interleaved for coalesced per-h row streaming:
// float4 index (j>>2)*HN + h holds Wr[h][4j..4j+3]
__device__ float g_wri[(size_t)HN * HN];

// ---------------------------------------------------------------------------
// Kernel 1: FX = x @ Win^T, strict sequential-k FMA chain per output.
// ---------------------------------------------------------------------------
__global__ void __launch_bounds__(512, 1)
fx_kernel(const float* __restrict__ x, const float* __restrict__ Win) {
    __shared__ __align__(16) float xs[64 * IND];
    const int tid = threadIdx.x;

    float w[32];
    const float4* wr4 = (const float4*)(Win + tid * IND);
#pragma unroll
    for (int k = 0; k < 8; k++) {
        float4 f = wr4[k];
        w[4 * k + 0] = f.x; w[4 * k + 1] = f.y;
        w[4 * k + 2] = f.z; w[4 * k + 3] = f.w;
    }

    const int pair0 = blockIdx.x * 64;
    ((float4*)xs)[tid] = ((const float4*)(x + (size_t)pair0 * IND))[tid];
    __syncthreads();

    float* outp = g_fx + (size_t)pair0 * HN + tid;
#pragma unroll 4
    for (int k = 0; k < 64; k++) {
        const float* xk = xs + k * IND;
        float acc = 0.0f;
#pragma unroll
        for (int i = 0; i < IND; i++) acc = __fmaf_rn(w[i], xk[i], acc);
        outp[(size_t)k * HN] = acc;
    }
}

// ---------------------------------------------------------------------------
// Kernel 2: Wr[h][j] = seq-chain_p fma(fl(l[p]*pin[h,p]), pout[j,p]), stored
// j-interleaved. Block = one h, thread = one j.
// ---------------------------------------------------------------------------
__global__ void __launch_bounds__(512, 1)
wr_kernel(const float* __restrict__ pin, const float* __restrict__ pout,
          const float* __restrict__ l) {
    __shared__ float lp[PN];
    const int h = blockIdx.x;
    const int j = threadIdx.x;
    if (j < PN) lp[j] = __fmul_rn(l[j], pin[h * PN + j]);
    __syncthreads();

    const float* pr = pout + j * PN;
    float acc = 0.0f;
#pragma unroll
    for (int p = 0; p < PN; p++) acc = __fmaf_rn(lp[p], pr[p], acc);

    g_wri[((size_t)(j >> 2) * HN + h) * 4 + (j & 3)] = acc;
}

// ---------------------------------------------------------------------------
// Kernel 3: sequential scan. block = one batch, thread = one neuron.
// rec = exact 512-term sequential FMA chain over dense Wr (bit-match probe).
// ---------------------------------------------------------------------------
__global__ void __launch_bounds__(512, 1)
snn_kernel(const float* __restrict__ Wout, float* __restrict__ out,
           float arg_ls, float arg_lm, float arg_ld,
           float rgain, float dtc, float tref)
{
    __shared__ __align__(16) float woutT_sh[HN * ON];  // Wout^T[h][o]
    __shared__ __align__(16) float r_sh[HN];
    __shared__ float part_y[64];

    const int tid = threadIdx.x;
    const int b   = blockIdx.x;

    const float ls  = expf(arg_ls);
    const float lm  = expf(arg_lm);
    const float ldc = expf(arg_ld);
    const float olm = 1.0f - lm;

    for (int i = tid; i < HN * ON; i += 512) {
        int h = i >> 3, o = i & 7;
        woutT_sh[i] = Wout[o * HN + h];
    }
    r_sh[tid] = 0.0f;

    float I = 0.0f, mem = 0.0f, s = 0.0f, r = 0.0f, tlast = -1.0f;

    const float* fxg = g_fx + (size_t)b * HN + tid;
    float fx = fxg[0];

    const float4* wr4 = (const float4*)g_wri;   // (j>>2)*HN + h

    __syncthreads();

#pragma unroll 1
    for (int t = 0; t < TS; t++) {
        const int tn = (t < TS - 1) ? t + 1 : t;
        const float fxn = fxg[(size_t)tn * (BN * HN)];   // prefetch next drive

        // rec[h] = sequential-j FMA chain over dense Wr row (bit-match order)
        float rec = 0.0f;
#pragma unroll 8
        for (int j4 = 0; j4 < HN / 4; j4++) {
            const float4 q  = wr4[(size_t)j4 * HN + tid];   // coalesced LDG.128
            const float4 rv = ((const float4*)r_sh)[j4];    // broadcast LDS.128
            rec = __fmaf_rn(q.x, rv.x, rec);
            rec = __fmaf_rn(q.y, rv.y, rec);
            rec = __fmaf_rn(q.z, rv.z, rec);
            rec = __fmaf_rn(q.w, rv.w, rec);
        }

        // pointwise update (reference op order, no FMA contraction)
        I = __fadd_rn(__fadd_rn(__fmul_rn(ls, I), fx), rec);
        const float ti     = __fmul_rn(dtc, (float)t);
        const float notref = (ti > __fadd_rn(tlast, tref)) ? 1.0f : 0.0f;
        const float memn   = __fmul_rn(__fmul_rn(notref,
                                __fadd_rn(__fmul_rn(lm, mem), __fmul_rn(olm, I))),
                                __fsub_rn(1.0f, s));
        // r uses PREVIOUS-step spike s
        r = __fadd_rn(__fmul_rn(ldc, r), __fmul_rn(rgain, s));

        const float snew = (__fsub_rn(memn, 1.0f) > 0.0f) ? 1.0f : 0.0f;
        tlast = __fadd_rn(tlast, __fmul_rn(__fsub_rn(ti, tlast), snew));
        mem = memn; s = snew; fx = fxn;

        __syncthreads();          // all rec chains done reading r_sh
        r_sh[tid] = r;            // publish r(t)
        __syncthreads();          // r(t) visible

        // y partials (outside the feedback loop; fast order is fine)
        if (tid >= 448) {
            const int idx = tid - 448;
            const int o = idx & 7, seg = idx >> 3;
            const float* wp = woutT_sh + (seg << 6) * 8 + o;
            const float* rr = r_sh + (seg << 6);
            float e0 = 0.0f, e1 = 0.0f;
#pragma unroll
            for (int hh = 0; hh < 64; hh += 2) {
                e0 = __fmaf_rn(wp[hh << 3],       rr[hh],     e0);
                e1 = __fmaf_rn(wp[(hh + 1) << 3], rr[hh + 1], e1);
            }
            part_y[idx] = e0 + e1;
        }
        __syncthreads();          // partials visible

        if (tid < ON) {
            const float* q = part_y + tid;
            float v = ((q[0] + q[8]) + (q[16] + q[24])) +
                      ((q[32] + q[40]) + (q[48] + q[56]));
            out[((size_t)t * BN + b) * ON + tid] = v;
        }
        // next iteration's chain reads r_sh (no writer until next publish)
    }
}

extern "C" void kernel_launch(void* const* d_in, const int* in_sizes, int n_in,
                              void* d_out, int out_size) {
    const float* x    = (const float*)d_in[0];
    const float* Win  = (const float*)d_in[1];
    const float* Wout = (const float*)d_in[2];
    const float* pin  = (const float*)d_in[3];
    const float* pout = (const float*)d_in[4];
    const float* l    = (const float*)d_in[5];
    float* out = (float*)d_out;

    // Arguments computed exactly as JAX does: double divide, then f32 cast.
    const float arg_ls = (float)(-0.002 / 0.01);
    const float arg_lm = (float)(-0.002 / 0.02);
    const float arg_ld = (float)(-0.002 / 0.03);
    const float rgain  = (float)(0.002 / 0.03);
    const float dtc    = (float)0.002;
    const float tref   = (float)(5.0 * 0.002);

    fx_kernel<<<(TS * BN) / 64, 512>>>(x, Win);
    wr_kernel<<<HN, 512>>>(pin, pout, l);
    snn_kernel<<<BN, 512>>>(Wout, out, arg_ls, arg_lm, arg_ld, rgain, dtc, tref);
}

// round 7
// speedup vs baseline: 1.0011x; 1.0011x over previous
#include <cuda_runtime.h>
#include <math.h>

#define TS 512
#define BN 128
#define IND 32
#define HN 512
#define ON 8
#define PN 64

// FX[t,b,h] = sum_i Win[h,i]*x[t,b,i]  (134 MB scratch)
__device__ float g_fx[(size_t)TS * BN * HN];
// Wr in h-pair/j-pair interleaved layout: float4 at [(j>>1)*256 + (h>>1)] =
// ( W[h0][j], W[h1][j], W[h0][j+1], W[h1][j+1] ),  h0=2*(h>>1), h1=h0+1.
__device__ float g_wr2[(size_t)HN * HN];

typedef unsigned long long ull;

__device__ __forceinline__ ull ffma2(ull a, ull b, ull c) {
    ull d; asm("fma.rn.f32x2 %0,%1,%2,%3;" : "=l"(d) : "l"(a), "l"(b), "l"(c)); return d;
}
__device__ __forceinline__ ull pk2(float x, float y) {
    ull d; asm("mov.b64 %0,{%1,%2};" : "=l"(d) : "f"(x), "f"(y)); return d;
}
__device__ __forceinline__ void unpk2(ull a, float& lo, float& hi) {
    asm("mov.b64 {%0,%1},%2;" : "=f"(lo), "=f"(hi) : "l"(a));
}
__device__ __forceinline__ unsigned smem_u32(const void* p) {
    unsigned a;
    asm("{ .reg .u64 t; cvta.to.shared.u64 t, %1; cvt.u32.u64 %0, t; }"
        : "=r"(a) : "l"(p));
    return a;
}

// ---------------------------------------------------------------------------
// Kernel 1: FX = x @ Win^T, strict sequential-k FMA chain (bit-locked).
// ---------------------------------------------------------------------------
__global__ void __launch_bounds__(512, 1)
fx_kernel(const float* __restrict__ x, const float* __restrict__ Win) {
    __shared__ __align__(16) float xs[64 * IND];
    const int tid = threadIdx.x;

    float w[32];
    const float4* wr4 = (const float4*)(Win + tid * IND);
#pragma unroll
    for (int k = 0; k < 8; k++) {
        float4 f = wr4[k];
        w[4 * k + 0] = f.x; w[4 * k + 1] = f.y;
        w[4 * k + 2] = f.z; w[4 * k + 3] = f.w;
    }

    const int pair0 = blockIdx.x * 64;
    ((float4*)xs)[tid] = ((const float4*)(x + (size_t)pair0 * IND))[tid];
    __syncthreads();

    float* outp = g_fx + (size_t)pair0 * HN + tid;
#pragma unroll 4
    for (int k = 0; k < 64; k++) {
        const float* xk = xs + k * IND;
        float acc = 0.0f;
#pragma unroll
        for (int i = 0; i < IND; i++) acc = __fmaf_rn(w[i], xk[i], acc);
        outp[(size_t)k * HN] = acc;
    }
}

// ---------------------------------------------------------------------------
// Kernel 2: Wr[h][j] via sequential-p chain (bit-locked), stored h/j-pair
// interleaved for the FFMA2 scan. Block = one h, thread = one j.
// ---------------------------------------------------------------------------
__global__ void __launch_bounds__(512, 1)
wr_kernel(const float* __restrict__ pin, const float* __restrict__ pout,
          const float* __restrict__ l) {
    __shared__ float lp[PN];
    const int h = blockIdx.x;
    const int j = threadIdx.x;
    if (j < PN) lp[j] = __fmul_rn(l[j], pin[h * PN + j]);
    __syncthreads();

    const float* pr = pout + j * PN;
    float acc = 0.0f;
#pragma unroll
    for (int p = 0; p < PN; p++) acc = __fmaf_rn(lp[p], pr[p], acc);

    const size_t q4 = (size_t)(j >> 1) * 256 + (h >> 1);
    g_wr2[q4 * 4 + (h & 1) + 2 * (j & 1)] = acc;
}

// ---------------------------------------------------------------------------
// Kernel 3: scan. cluster of 2 blocks = one batch PAIR; block u owns 256 h's.
// 128 threads, thread = h-pair (h0=u*256+2*tid, h1=h0+1) x 2 batches:
// two FFMA2 chains, lane-exact vs R6's scalar chains.
// r exchanged per step via DSMEM (duplicated pairs), double-buffered,
// one barrier.cluster per step.
// ---------------------------------------------------------------------------
__global__ void __launch_bounds__(128, 1) __cluster_dims__(2, 1, 1)
snn_kernel(const float* __restrict__ Wout, float* __restrict__ out,
           float arg_ls, float arg_lm, float arg_ld,
           float rgain, float dtc, float tref)
{
    __shared__ __align__(16) ull rdup[2][2][HN];     // [parity][batch][h]: (r,r)
    __shared__ __align__(16) float woutT_sh[HN * ON];
    __shared__ float part_y[64];

    const int tid = threadIdx.x;
    const int p   = blockIdx.x >> 1;    // batch pair id
    const int u   = blockIdx.x & 1;     // h-half
    const int b0  = 2 * p;
    const int bu  = 2 * p + u;          // batch this block emits y for

    const float ls  = expf(arg_ls);
    const float lm  = expf(arg_lm);
    const float ldc = expf(arg_ld);
    const float olm = 1.0f - lm;

    for (int i = tid; i < HN * ON; i += 128)
        woutT_sh[i] = Wout[(i & 7) * HN + (i >> 3)];
    // zero parity-0 r buffers (both batches)
    for (int i = tid; i < 2 * HN; i += 128) ((ull*)rdup)[i] = 0ull;

    const int h0 = u * 256 + 2 * tid;

    // peer DSMEM base for rdup
    const unsigned rd_local = smem_u32(&rdup[0][0][0]);
    unsigned rd_peer;
    asm("mapa.shared::cluster.u32 %0, %1, %2;" : "=r"(rd_peer)
        : "r"(rd_local), "r"(u ^ 1));

    // neuron state: [hh][bb]
    float I[2][2]   = {{0.f,0.f},{0.f,0.f}};
    float mem[2][2] = {{0.f,0.f},{0.f,0.f}};
    float s[2][2]   = {{0.f,0.f},{0.f,0.f}};
    float r[2][2]   = {{0.f,0.f},{0.f,0.f}};
    float tl[2][2]  = {{-1.f,-1.f},{-1.f,-1.f}};

    const float2* fx0 = (const float2*)(g_fx + (size_t)b0 * HN + h0);
    const float2* fx1 = (const float2*)(g_fx + (size_t)(b0 + 1) * HN + h0);
    float2 fxc0 = fx0[0], fxc1 = fx1[0];

    const ulonglong2* wp = (const ulonglong2*)g_wr2 + (u * 128 + tid);
    const float* rlow = (const float*)&rdup[0][0][0];  // lane-0 view of pairs

    __syncthreads();

#pragma unroll 1
    for (int t = 0; t < TS; t++) {
        const int par = t & 1;
        const int tn = (t < TS - 1) ? t + 1 : t;
        const float2 fxn0 = fx0[(size_t)tn * (BN * HN / 2)];   // prefetch
        const float2 fxn1 = fx1[(size_t)tn * (BN * HN / 2)];

        // two FFMA2 chains: rec_b0=(rec[h0][b0],rec[h1][b0]), rec_b1 likewise.
        // Sequential in j per lane — bit-identical to the scalar chain.
        const ulonglong2* d0 = (const ulonglong2*)&rdup[par][0][0];
        const ulonglong2* d1 = (const ulonglong2*)&rdup[par][1][0];
        ull rec_b0 = 0ull, rec_b1 = 0ull;
#pragma unroll 16
        for (int j2 = 0; j2 < 256; j2++) {
            const ulonglong2 q  = wp[(size_t)j2 * 256];  // (h0,h1)@j, (h0,h1)@j+1
            const ulonglong2 r0 = d0[j2];                // (r,r)@j, (r,r)@j+1
            const ulonglong2 r1 = d1[j2];
            rec_b0 = ffma2(q.x, r0.x, rec_b0);
            rec_b0 = ffma2(q.y, r0.y, rec_b0);
            rec_b1 = ffma2(q.x, r1.x, rec_b1);
            rec_b1 = ffma2(q.y, r1.y, rec_b1);
        }
        float rec[2][2], fxv[2][2];
        unpk2(rec_b0, rec[0][0], rec[1][0]);
        unpk2(rec_b1, rec[0][1], rec[1][1]);
        fxv[0][0] = fxc0.x; fxv[1][0] = fxc0.y;
        fxv[0][1] = fxc1.x; fxv[1][1] = fxc1.y;

        const float ti = __fmul_rn(dtc, (float)t);
#pragma unroll
        for (int hh = 0; hh < 2; hh++)
#pragma unroll
            for (int bb = 0; bb < 2; bb++) {
                I[hh][bb] = __fadd_rn(__fadd_rn(__fmul_rn(ls, I[hh][bb]),
                                                fxv[hh][bb]), rec[hh][bb]);
                const float notref = (ti > __fadd_rn(tl[hh][bb], tref)) ? 1.0f : 0.0f;
                const float memn = __fmul_rn(__fmul_rn(notref,
                        __fadd_rn(__fmul_rn(lm, mem[hh][bb]),
                                  __fmul_rn(olm, I[hh][bb]))),
                        __fsub_rn(1.0f, s[hh][bb]));
                r[hh][bb] = __fadd_rn(__fmul_rn(ldc, r[hh][bb]),
                                      __fmul_rn(rgain, s[hh][bb]));
                const float snew = (__fsub_rn(memn, 1.0f) > 0.0f) ? 1.0f : 0.0f;
                tl[hh][bb] = __fadd_rn(tl[hh][bb],
                               __fmul_rn(__fsub_rn(ti, tl[hh][bb]), snew));
                mem[hh][bb] = memn; s[hh][bb] = snew;
            }
        fxc0 = fxn0; fxc1 = fxn1;

        // publish r(t) into parity par^1, duplicated, local + peer
        {
            const int pn = par ^ 1;
#pragma unroll
            for (int hh = 0; hh < 2; hh++)
#pragma unroll
                for (int bb = 0; bb < 2; bb++) {
                    const ull v = pk2(r[hh][bb], r[hh][bb]);
                    const unsigned off = ((unsigned)(pn * 2 + bb) * HN + h0 + hh) * 8u;
                    asm volatile("st.shared.b64 [%0], %1;"
                                 :: "r"(rd_local + off), "l"(v) : "memory");
                    asm volatile("st.shared::cluster.b64 [%0], %1;"
                                 :: "r"(rd_peer + off), "l"(v) : "memory");
                }
        }
        // one cluster barrier: release local+peer stores, acquire peer's
        asm volatile("barrier.cluster.arrive.aligned;" ::: "memory");
        asm volatile("barrier.cluster.wait.aligned;"   ::: "memory");

        // y for batch bu from full r(t) (same order as R6)
        if (tid < 64) {
            const int o = tid & 7, seg = tid >> 3;
            const float* wq = woutT_sh + (seg << 6) * 8 + o;
            const float* rr = rlow + ((size_t)((par ^ 1) * 2 + u) * HN + (seg << 6)) * 2;
            float e0 = 0.0f, e1 = 0.0f;
#pragma unroll
            for (int hh = 0; hh < 64; hh += 2) {
                e0 = __fmaf_rn(wq[hh << 3],       rr[hh * 2],       e0);
                e1 = __fmaf_rn(wq[(hh + 1) << 3], rr[(hh + 1) * 2], e1);
            }
            part_y[tid] = e0 + e1;
        }
        __syncthreads();
        if (tid < ON) {
            const float* q = part_y + tid;
            float v = ((q[0] + q[8]) + (q[16] + q[24])) +
                      ((q[32] + q[40]) + (q[48] + q[56]));
            out[((size_t)t * BN + bu) * ON + tid] = v;
        }
    }
}

extern "C" void kernel_launch(void* const* d_in, const int* in_sizes, int n_in,
                              void* d_out, int out_size) {
    const float* x    = (const float*)d_in[0];
    const float* Win  = (const float*)d_in[1];
    const float* Wout = (const float*)d_in[2];
    const float* pin  = (const float*)d_in[3];
    const float* pout = (const float*)d_in[4];
    const float* l    = (const float*)d_in[5];
    float* out = (float*)d_out;

    const float arg_ls = (float)(-0.002 / 0.01);
    const float arg_lm = (float)(-0.002 / 0.02);
    const float arg_ld = (float)(-0.002 / 0.03);
    const float rgain  = (float)(0.002 / 0.03);
    const float dtc    = (float)0.002;
    const float tref   = (float)(5.0 * 0.002);

    fx_kernel<<<(TS * BN) / 64, 512>>>(x, Win);
    wr_kernel<<<HN, 512>>>(pin, pout, l);
    snn_kernel<<<BN, 128>>>(Wout, out, arg_ls, arg_lm, arg_ld, rgain, dtc, tref);
}